// round 8
// baseline (speedup 1.0000x reference)
#include <cuda_runtime.h>
#include <cuda_bf16.h>
#include <math.h>
#include <cstdint>

#define T_   64
#define P_   144
#define C_   1024
#define MID_ 256
#define ROWS (T_ * P_)   // 9216

// ---------------- scratch (no allocations allowed) ----------------
__device__ float          g_q[ROWS * MID_];   //  9.4 MB
__device__ __nv_bfloat16  g_r[ROWS * C_];     // 18.9 MB
__device__ float          g_WT[MID_ * C_];    //  1.0 MB  (Wq^T)

__device__ __forceinline__ uint32_t f2tf32(float x) {
    uint32_t r;
    asm("cvt.rna.tf32.f32 %0, %1;" : "=r"(r) : "f"(x));
    return r;
}
__device__ __forceinline__ uint4 cvt4(float4 v) {
    return make_uint4(f2tf32(v.x), f2tf32(v.y), f2tf32(v.z), f2tf32(v.w));
}
__device__ __forceinline__ uint32_t smem_u32(const void* p) {
    uint32_t a;
    asm("{ .reg .u64 t; cvta.to.shared.u64 t, %1; cvt.u32.u64 %0, t; }"
        : "=r"(a) : "l"(p));
    return a;
}
__device__ __forceinline__ void ldsm4(uint32_t& r0, uint32_t& r1,
                                      uint32_t& r2, uint32_t& r3, uint32_t addr) {
    asm volatile("ldmatrix.sync.aligned.m8n8.x4.shared.b16 {%0,%1,%2,%3}, [%4];"
                 : "=r"(r0), "=r"(r1), "=r"(r2), "=r"(r3) : "r"(addr));
}
__device__ __forceinline__ void mma_tf32(float& c0, float& c1, float& c2, float& c3,
                                         uint32_t a0, uint32_t a1, uint32_t a2, uint32_t a3,
                                         uint32_t b0, uint32_t b1) {
    asm volatile(
        "mma.sync.aligned.m16n8k8.row.col.f32.tf32.tf32.f32 "
        "{%0,%1,%2,%3}, {%4,%5,%6,%7}, {%8,%9}, {%0,%1,%2,%3};"
        : "+f"(c0), "+f"(c1), "+f"(c2), "+f"(c3)
        : "r"(a0), "r"(a1), "r"(a2), "r"(a3), "r"(b0), "r"(b1));
}

// ---------------- transpose Wq [1024,256] -> WT [256,1024] ----------------
__global__ void transpose_w(const float* __restrict__ W) {
    __shared__ float s[32][33];
    int c0 = blockIdx.x * 32;
    int d0 = blockIdx.y * 32;
    int tx = threadIdx.x, ty = threadIdx.y;  // 32 x 8
#pragma unroll
    for (int u = 0; u < 32; u += 8)
        s[ty + u][tx] = W[(size_t)(c0 + ty + u) * MID_ + d0 + tx];
    __syncthreads();
#pragma unroll
    for (int u = 0; u < 32; u += 8)
        g_WT[(size_t)(d0 + ty + u) * C_ + c0 + tx] = s[tx][ty + u];
}

// ---------------- tf32 mma.sync GEMM with ldmatrix fragments ----------------
// D[M,N] = A[M,K](row-major) @ B[N,K]^T (+bias). BM=128, BN=64, BK=32.
// POOL: A-rows are 2x2 window means of x [64,576,1024] (pool fused into loader).
// BF16OUT: store result as bf16.
// 128 threads = 4 warps, 2(m) x 2(n); warp tile 64x32.
// Smem XOR-swizzled: word (row,k) at row*32 + (k ^ ((row&7)<<2)).
template <bool POOL, bool BF16OUT>
__global__ void __launch_bounds__(128)
gemm_mma(const float* __restrict__ Aop, const float* __restrict__ B,
         const float* __restrict__ bias, void* __restrict__ CoutV,
         const int N, const int K) {
    __shared__ uint32_t As[128 * 32];
    __shared__ uint32_t Bs[64 * 32];
    __shared__ float sBias[64];

    const int tid = threadIdx.x;
    const int lane = tid & 31, wid = tid >> 5;
    const int warp_m = wid >> 1, warp_n = wid & 1;
    const int bm = blockIdx.y * 128, bn = blockIdx.x * 64;

    if (tid < 64) sBias[tid] = bias ? bias[bn + tid] : 0.0f;

    const uint32_t uA = smem_u32(As);
    const uint32_t uB = smem_u32(Bs);

    // ---- ldmatrix per-thread address components ----
    const int lrow8 = lane & 7;
    const int lsel  = (lane >> 3) & 1;   // +8 rows (A) / k-half (B)
    const int lkh   = lane >> 4;         // k-half (A) / nt-pair member (B)

    // A: for each mt, this lane supplies one 16B row of one of the 4 matrices
    uint32_t aAddrBase[4];  // word index row*32; swizzle salt per mt
    int aSw[4];
#pragma unroll
    for (int mt = 0; mt < 4; mt++) {
        int rowA = warp_m * 64 + mt * 16 + lsel * 8 + lrow8;
        aAddrBase[mt] = (uint32_t)rowA * 32;
        aSw[mt] = (rowA & 7) << 2;
    }
    // B: pair b covers ntiles {2b, 2b+1}
    uint32_t bAddrBase[2];
    int bSw[2];
#pragma unroll
    for (int b = 0; b < 2; b++) {
        int rowB = warp_n * 32 + (2 * b + lkh) * 8 + lrow8;
        bAddrBase[b] = (uint32_t)rowB * 32;
        bSw[b] = (rowB & 7) << 2;
    }
    const int aKh = lkh * 4;   // A k-half offset for this lane
    const int bKh = lsel * 4;  // B k-half offset for this lane

    // ---- global staging mapping: 8 float4 cols over K-chunk, 16-row strides
    const int lcol = tid & 7;     // float4 column (k/4)
    const int lrow = tid >> 3;    // 0..15

    const float* aptr[8];
#pragma unroll
    for (int it = 0; it < 8; it++) {
        int rg = bm + lrow + it * 16;
        if (POOL) {
            int t = rg / P_, p = rg % P_;
            int i = p / 12, j = p % 12;
            aptr[it] = Aop + ((size_t)t * 576 + (size_t)(2 * i) * 24 + 2 * j) * C_
                           + lcol * 4;
        } else {
            aptr[it] = Aop + (size_t)rg * K + lcol * 4;
        }
    }
    const float* bptr = B + (size_t)(bn + lrow) * K + lcol * 4;

    float acc[4][4][4];
#pragma unroll
    for (int i = 0; i < 4; i++)
#pragma unroll
        for (int j = 0; j < 4; j++)
#pragma unroll
            for (int f = 0; f < 4; f++) acc[i][j][f] = 0.0f;

    const int stSw = (lcol * 4);  // store column base (words)

    for (int k0 = 0; k0 < K; k0 += 32) {
        // ---- stage A tile ----
#pragma unroll
        for (int it = 0; it < 8; it++) {
            float4 a;
            if (POOL) {
                const float* p = aptr[it] + k0;
                float4 v0 = *(const float4*)(p);
                float4 v1 = *(const float4*)(p + C_);
                float4 v2 = *(const float4*)(p + 24 * C_);
                float4 v3 = *(const float4*)(p + 25 * C_);
                a.x = 0.25f * ((v0.x + v1.x) + (v2.x + v3.x));
                a.y = 0.25f * ((v0.y + v1.y) + (v2.y + v3.y));
                a.z = 0.25f * ((v0.z + v1.z) + (v2.z + v3.z));
                a.w = 0.25f * ((v0.w + v1.w) + (v2.w + v3.w));
            } else {
                a = *(const float4*)(aptr[it] + k0);
            }
            int row = lrow + it * 16;
            int off = row * 32 + (stSw ^ ((row & 7) << 2));
            *(uint4*)&As[off] = cvt4(a);
        }
        // ---- stage B tile ----
#pragma unroll
        for (int it = 0; it < 4; it++) {
            float4 v = *(const float4*)(bptr + (size_t)it * 16 * K + k0);
            int row = lrow + it * 16;
            int off = row * 32 + (stSw ^ ((row & 7) << 2));
            *(uint4*)&Bs[off] = cvt4(v);
        }
        __syncthreads();

        // ---- compute: 4 k-steps, ldmatrix fragments ----
#pragma unroll
        for (int ks = 0; ks < 4; ks++) {
            uint32_t af[4][4];
#pragma unroll
            for (int mt = 0; mt < 4; mt++) {
                uint32_t addr = uA + 4u * (aAddrBase[mt] +
                                (uint32_t)((ks * 8 + aKh) ^ aSw[mt]));
                ldsm4(af[mt][0], af[mt][1], af[mt][2], af[mt][3], addr);
            }
            uint32_t bf[4][2];
#pragma unroll
            for (int b = 0; b < 2; b++) {
                uint32_t addr = uB + 4u * (bAddrBase[b] +
                                (uint32_t)((ks * 8 + bKh) ^ bSw[b]));
                ldsm4(bf[2 * b][0], bf[2 * b][1], bf[2 * b + 1][0], bf[2 * b + 1][1],
                      addr);
            }
#pragma unroll
            for (int mt = 0; mt < 4; mt++)
#pragma unroll
                for (int nt = 0; nt < 4; nt++)
                    mma_tf32(acc[mt][nt][0], acc[mt][nt][1],
                             acc[mt][nt][2], acc[mt][nt][3],
                             af[mt][0], af[mt][1], af[mt][2], af[mt][3],
                             bf[nt][0], bf[nt][1]);
        }
        __syncthreads();
    }

    // ---- epilogue ----
    const int g = lane >> 2, tk = lane & 3;
#pragma unroll
    for (int mt = 0; mt < 4; mt++) {
#pragma unroll
        for (int nt = 0; nt < 4; nt++) {
            int r = bm + warp_m * 64 + mt * 16 + g;
            int cbase = warp_n * 32 + nt * 8 + tk * 2;
            float b0 = sBias[cbase], b1 = sBias[cbase + 1];
            int cg = bn + cbase;
            if (BF16OUT) {
                __nv_bfloat16* o = (__nv_bfloat16*)CoutV;
                *(__nv_bfloat162*)(o + (size_t)r * N + cg) =
                    __floats2bfloat162_rn(acc[mt][nt][0] + b0, acc[mt][nt][1] + b1);
                *(__nv_bfloat162*)(o + (size_t)(r + 8) * N + cg) =
                    __floats2bfloat162_rn(acc[mt][nt][2] + b0, acc[mt][nt][3] + b1);
            } else {
                float* o = (float*)CoutV;
                *(float2*)(o + (size_t)r * N + cg) =
                    make_float2(acc[mt][nt][0] + b0, acc[mt][nt][1] + b1);
                *(float2*)(o + (size_t)(r + 8) * N + cg) =
                    make_float2(acc[mt][nt][2] + b0, acc[mt][nt][3] + b1);
            }
        }
    }
}

// ---------------- attention dots + softmax + weighted epilogue ----------------
__global__ void attn_kernel(const float* __restrict__ x, const float* __restrict__ bk,
                            float* __restrict__ out) {
    int row = blockIdx.x;
    int t = row / P_, p = row % P_;
    int i = p / 12, j = p % 12;
    const float* xb = x + ((size_t)t * 576 + (size_t)(2 * i) * 24 + 2 * j) * C_;
    const __nv_bfloat16* rr = g_r + (size_t)row * C_;
    int tid = threadIdx.x;
    int c = tid * 4;

    const __nv_bfloat162* rp = (const __nv_bfloat162*)(rr + c);
    float2 r01 = __bfloat1622float2(rp[0]);
    float2 r23 = __bfloat1622float2(rp[1]);
    float4 rv = make_float4(r01.x, r01.y, r23.x, r23.y);

    float4 x0 = *(const float4*)(xb + c);
    float4 x1 = *(const float4*)(xb + C_ + c);
    float4 x2 = *(const float4*)(xb + 24 * C_ + c);
    float4 x3 = *(const float4*)(xb + 25 * C_ + c);

    float s0 = rv.x * x0.x + rv.y * x0.y + rv.z * x0.z + rv.w * x0.w;
    float s1 = rv.x * x1.x + rv.y * x1.y + rv.z * x1.z + rv.w * x1.w;
    float s2 = rv.x * x2.x + rv.y * x2.y + rv.z * x2.z + rv.w * x2.w;
    float s3 = rv.x * x3.x + rv.y * x3.y + rv.z * x3.z + rv.w * x3.w;
    float qb = g_q[(size_t)row * MID_ + tid] * bk[tid];

#pragma unroll
    for (int off = 16; off > 0; off >>= 1) {
        s0 += __shfl_down_sync(0xffffffff, s0, off);
        s1 += __shfl_down_sync(0xffffffff, s1, off);
        s2 += __shfl_down_sync(0xffffffff, s2, off);
        s3 += __shfl_down_sync(0xffffffff, s3, off);
        qb += __shfl_down_sync(0xffffffff, qb, off);
    }

    __shared__ float red[8][5];
    __shared__ float coef[4];
    int lane = tid & 31, warp = tid >> 5;
    if (lane == 0) {
        red[warp][0] = s0; red[warp][1] = s1; red[warp][2] = s2;
        red[warp][3] = s3; red[warp][4] = qb;
    }
    __syncthreads();
    if (tid == 0) {
        float S[5] = {0.f, 0.f, 0.f, 0.f, 0.f};
#pragma unroll
        for (int w = 0; w < 8; w++)
#pragma unroll
            for (int k = 0; k < 5; k++) S[k] += red[w][k];
        const float scale = 0.0625f;  // 1/sqrt(256)
        float l0 = (S[0] + S[4]) * scale;
        float l1 = (S[1] + S[4]) * scale;
        float l2 = (S[2] + S[4]) * scale;
        float l3 = (S[3] + S[4]) * scale;
        float m = fmaxf(fmaxf(l0, l1), fmaxf(l2, l3));
        float e0 = expf(l0 - m), e1 = expf(l1 - m);
        float e2 = expf(l2 - m), e3 = expf(l3 - m);
        float inv = 1.0f / (e0 + e1 + e2 + e3);
        coef[0] = 0.25f + e0 * inv;
        coef[1] = 0.25f + e1 * inv;
        coef[2] = 0.25f + e2 * inv;
        coef[3] = 0.25f + e3 * inv;
    }
    __syncthreads();
    float c0 = coef[0], c1 = coef[1], c2 = coef[2], c3 = coef[3];
    float4 o;
    o.x = c0 * x0.x + c1 * x1.x + c2 * x2.x + c3 * x3.x;
    o.y = c0 * x0.y + c1 * x1.y + c2 * x2.y + c3 * x3.y;
    o.z = c0 * x0.z + c1 * x1.z + c2 * x2.z + c3 * x3.z;
    o.w = c0 * x0.w + c1 * x1.w + c2 * x2.w + c3 * x3.w;
    *(float4*)(out + (size_t)row * C_ + c) = o;
}

// ---------------- launch ----------------
extern "C" void kernel_launch(void* const* d_in, const int* in_sizes, int n_in,
                              void* d_out, int out_size) {
    const float* x  = (const float*)d_in[0];  // [64, 576, 1024]
    const float* Wq = (const float*)d_in[1];  // [1024, 256]
    const float* bq = (const float*)d_in[2];  // [256]
    const float* Wk = (const float*)d_in[3];  // [1024, 256]
    const float* bk = (const float*)d_in[4];  // [256]
    float* out = (float*)d_out;               // [64, 144, 1024]

    float* q;           cudaGetSymbolAddress((void**)&q, g_q);
    __nv_bfloat16* r;   cudaGetSymbolAddress((void**)&r, g_r);
    float* wt;          cudaGetSymbolAddress((void**)&wt, g_WT);

    transpose_w<<<dim3(32, 8), dim3(32, 8)>>>(Wq);
    // q[9216,256] = pool2x2(x)[9216,1024] @ Wq + bq   (pool fused into A loader)
    gemm_mma<true, false><<<dim3(MID_ / 64, ROWS / 128), 128>>>(x, wt, bq, q, MID_, C_);
    // r[9216,1024] = q[9216,256] @ Wk^T   (bf16 out; B = Wk as-is, K-major rows)
    gemm_mma<false, true><<<dim3(C_ / 64, ROWS / 128), 128>>>(q, Wk, nullptr, r, C_, MID_);
    attn_kernel<<<ROWS, 256>>>(x, bk, out);
}

// round 9
// speedup vs baseline: 2.0202x; 2.0202x over previous
#include <cuda_runtime.h>
#include <math.h>
#include <cstdint>

#define T_   64
#define P_   144
#define C_   1024
#define MID_ 256
#define ROWS (T_ * P_)   // 9216

// ---------------- scratch (no allocations allowed) ----------------
__device__ float g_pooled[ROWS * C_];   // 37.7 MB (tf32-rounded)
__device__ float g_q[ROWS * MID_];      //  9.4 MB (tf32-rounded)
__device__ float g_r[ROWS * C_];        // 37.7 MB
__device__ float g_WT[MID_ * C_];       //  1.0 MB (Wq^T, tf32-rounded)
__device__ float g_WkR[C_ * MID_];      //  1.0 MB (Wk, tf32-rounded)

__device__ __forceinline__ uint32_t f2tf32(float x) {
    uint32_t r;
    asm("cvt.rna.tf32.f32 %0, %1;" : "=r"(r) : "f"(x));
    return r;
}
__device__ __forceinline__ float rnd_tf32(float x) {
    return __uint_as_float(f2tf32(x));
}
__device__ __forceinline__ uint32_t smem_u32(const void* p) {
    uint32_t a;
    asm("{ .reg .u64 t; cvta.to.shared.u64 t, %1; cvt.u32.u64 %0, t; }"
        : "=r"(a) : "l"(p));
    return a;
}
__device__ __forceinline__ void cpasync16(uint32_t s, const float* g) {
    asm volatile("cp.async.cg.shared.global [%0], [%1], 16;" :: "r"(s), "l"(g));
}
#define CP_COMMIT() asm volatile("cp.async.commit_group;" ::: "memory")
#define CP_WAIT(N)  asm volatile("cp.async.wait_group %0;" :: "n"(N) : "memory")

__device__ __forceinline__ void mma_tf32(float& c0, float& c1, float& c2, float& c3,
                                         uint32_t a0, uint32_t a1, uint32_t a2, uint32_t a3,
                                         uint32_t b0, uint32_t b1) {
    asm volatile(
        "mma.sync.aligned.m16n8k8.row.col.f32.tf32.tf32.f32 "
        "{%0,%1,%2,%3}, {%4,%5,%6,%7}, {%8,%9}, {%0,%1,%2,%3};"
        : "+f"(c0), "+f"(c1), "+f"(c2), "+f"(c3)
        : "r"(a0), "r"(a1), "r"(a2), "r"(a3), "r"(b0), "r"(b1));
}

// ---------------- K1: 2x2 window average pool (tf32-rounded output) ------------
__global__ void pool_kernel(const float* __restrict__ x) {
    int row = blockIdx.x;
    int t = row / P_, p = row % P_;
    int i = p / 12, j = p % 12;
    const float* base = x + ((size_t)t * 576 + (size_t)(2 * i) * 24 + 2 * j) * C_;
    int c = threadIdx.x * 4;
    float4 a = *(const float4*)(base + c);
    float4 b = *(const float4*)(base + C_ + c);
    float4 d = *(const float4*)(base + 24 * C_ + c);
    float4 e = *(const float4*)(base + 25 * C_ + c);
    float4 o;
    o.x = rnd_tf32(0.25f * ((a.x + b.x) + (d.x + e.x)));
    o.y = rnd_tf32(0.25f * ((a.y + b.y) + (d.y + e.y)));
    o.z = rnd_tf32(0.25f * ((a.z + b.z) + (d.z + e.z)));
    o.w = rnd_tf32(0.25f * ((a.w + b.w) + (d.w + e.w)));
    *(float4*)(g_pooled + (size_t)row * C_ + c) = o;
}

// ---------------- K2a: transpose Wq -> WT (tf32-rounded) ----------------
__global__ void transpose_w(const float* __restrict__ W) {
    __shared__ float s[32][33];
    int c0 = blockIdx.x * 32;
    int d0 = blockIdx.y * 32;
    int tx = threadIdx.x, ty = threadIdx.y;  // 32 x 8
#pragma unroll
    for (int u = 0; u < 32; u += 8)
        s[ty + u][tx] = W[(size_t)(c0 + ty + u) * MID_ + d0 + tx];
    __syncthreads();
#pragma unroll
    for (int u = 0; u < 32; u += 8)
        g_WT[(size_t)(d0 + ty + u) * C_ + c0 + tx] = rnd_tf32(s[tx][ty + u]);
}

// ---------------- K2b: round Wk to tf32 (copy) ----------------
__global__ void round_wk(const float* __restrict__ Wk) {
    int i = blockIdx.x * 256 + threadIdx.x;   // 256 blocks x 256 thr x float4
    float4 v = ((const float4*)Wk)[i];
    float4 o = make_float4(rnd_tf32(v.x), rnd_tf32(v.y), rnd_tf32(v.z), rnd_tf32(v.w));
    ((float4*)g_WkR)[i] = o;
}

// ---------------- tf32 mma.sync GEMM, cp.async 2-stage double buffer ----------
// D[M,N] = A[M,K](row-major, pre-rounded tf32) @ B[N,K]^T (+bias).
// BM=128, BN=64, BK=32. 128 threads = 4 warps, 2(m) x 2(n); warp tile 64x32.
// Smem XOR-swizzled: word (row,k) at row*32 + (k ^ ((row&7)<<2)).
template <bool BIAS, bool ROUNDOUT>
__global__ void __launch_bounds__(128)
gemm_cp(const float* __restrict__ A, const float* __restrict__ B,
        const float* __restrict__ bias, float* __restrict__ Cout,
        const int N, const int K) {
    __shared__ uint32_t As[2][128 * 32];
    __shared__ uint32_t Bs[2][64 * 32];
    __shared__ float sBias[64];

    const int tid = threadIdx.x;
    const int lane = tid & 31, wid = tid >> 5;
    const int warp_m = wid >> 1, warp_n = wid & 1;
    const int bm = blockIdx.y * 128, bn = blockIdx.x * 64;

    if (BIAS && tid < 64) sBias[tid] = bias[bn + tid];

    const int g = lane >> 2;      // group id 0..7
    const int tk = lane & 3;      // thread-in-group
    const int sw = g << 2;        // XOR swizzle for fragment loads

    // staging mapping: 8 float4 cols over K-chunk, 16-row strides
    const int lcol = tid & 7;     // float4 column (k/4)
    const int lrow = tid >> 3;    // 0..15

    const float* ag = A + (size_t)(bm + lrow) * K + lcol * 4;
    const float* bg = B + (size_t)(bn + lrow) * K + lcol * 4;

    // byte offsets of this thread's 16B store slots inside a buffer
    uint32_t aoff[8], boff[4];
#pragma unroll
    for (int it = 0; it < 8; it++) {
        int row = lrow + it * 16;
        aoff[it] = 4u * (uint32_t)(row * 32 + ((lcol * 4) ^ ((row & 7) << 2)));
    }
#pragma unroll
    for (int it = 0; it < 4; it++) {
        int row = lrow + it * 16;
        boff[it] = 4u * (uint32_t)(row * 32 + ((lcol * 4) ^ ((row & 7) << 2)));
    }
    const uint32_t uAb[2] = { smem_u32(As[0]), smem_u32(As[1]) };
    const uint32_t uBb[2] = { smem_u32(Bs[0]), smem_u32(Bs[1]) };

    float acc[4][4][4];
#pragma unroll
    for (int i = 0; i < 4; i++)
#pragma unroll
        for (int j = 0; j < 4; j++)
#pragma unroll
            for (int f = 0; f < 4; f++) acc[i][j][f] = 0.0f;

#define STAGE(BUF, K0)                                                         \
    {                                                                          \
        const int _k0 = (K0);                                                  \
        const uint32_t _ua = uAb[BUF], _ub = uBb[BUF];                         \
        _Pragma("unroll")                                                      \
        for (int it = 0; it < 8; it++)                                         \
            cpasync16(_ua + aoff[it], ag + (size_t)it * 16 * K + _k0);         \
        _Pragma("unroll")                                                      \
        for (int it = 0; it < 4; it++)                                         \
            cpasync16(_ub + boff[it], bg + (size_t)it * 16 * K + _k0);         \
    }

    // prologue
    STAGE(0, 0)
    CP_COMMIT();

    const int nch = K >> 5;
    for (int ck = 0; ck < nch; ck++) {
        const int buf = ck & 1;
        const bool more = (ck + 1) < nch;
        if (more) {
            STAGE(buf ^ 1, (ck + 1) << 5)
            CP_COMMIT();
            CP_WAIT(1);
        } else {
            CP_WAIT(0);
        }
        __syncthreads();

        const uint32_t* Ab = As[buf];
        const uint32_t* Bb = Bs[buf];
#pragma unroll
        for (int ks = 0; ks < 4; ks++) {
            const int kx  = (ks * 8 + tk) ^ sw;
            const int kx4 = kx ^ 4;

            uint32_t af[4][4];
#pragma unroll
            for (int mt = 0; mt < 4; mt++) {
                int r = warp_m * 64 + mt * 16 + g;
                af[mt][0] = Ab[r * 32 + kx];
                af[mt][1] = Ab[(r + 8) * 32 + kx];
                af[mt][2] = Ab[r * 32 + kx4];
                af[mt][3] = Ab[(r + 8) * 32 + kx4];
            }
            uint32_t bf[4][2];
#pragma unroll
            for (int nt = 0; nt < 4; nt++) {
                int n = warp_n * 32 + nt * 8 + g;
                bf[nt][0] = Bb[n * 32 + kx];
                bf[nt][1] = Bb[n * 32 + kx4];
            }
#pragma unroll
            for (int mt = 0; mt < 4; mt++)
#pragma unroll
                for (int nt = 0; nt < 4; nt++)
                    mma_tf32(acc[mt][nt][0], acc[mt][nt][1],
                             acc[mt][nt][2], acc[mt][nt][3],
                             af[mt][0], af[mt][1], af[mt][2], af[mt][3],
                             bf[nt][0], bf[nt][1]);
        }
        __syncthreads();
    }
#undef STAGE

    // epilogue
#pragma unroll
    for (int mt = 0; mt < 4; mt++) {
#pragma unroll
        for (int nt = 0; nt < 4; nt++) {
            int r = bm + warp_m * 64 + mt * 16 + g;
            int cbase = warp_n * 32 + nt * 8 + tk * 2;
            float b0 = BIAS ? sBias[cbase] : 0.0f;
            float b1 = BIAS ? sBias[cbase + 1] : 0.0f;
            int cg = bn + cbase;
            float v0 = acc[mt][nt][0] + b0, v1 = acc[mt][nt][1] + b1;
            float v2 = acc[mt][nt][2] + b0, v3 = acc[mt][nt][3] + b1;
            if (ROUNDOUT) {
                v0 = rnd_tf32(v0); v1 = rnd_tf32(v1);
                v2 = rnd_tf32(v2); v3 = rnd_tf32(v3);
            }
            *(float2*)(Cout + (size_t)r * N + cg) = make_float2(v0, v1);
            *(float2*)(Cout + (size_t)(r + 8) * N + cg) = make_float2(v2, v3);
        }
    }
}

// ---------------- K5: attention dots + softmax + weighted epilogue ----------------
__global__ void attn_kernel(const float* __restrict__ x, const float* __restrict__ bk,
                            float* __restrict__ out) {
    int row = blockIdx.x;
    int t = row / P_, p = row % P_;
    int i = p / 12, j = p % 12;
    const float* xb = x + ((size_t)t * 576 + (size_t)(2 * i) * 24 + 2 * j) * C_;
    const float* rr = g_r + (size_t)row * C_;
    int tid = threadIdx.x;
    int c = tid * 4;

    float4 rv = *(const float4*)(rr + c);
    float4 x0 = *(const float4*)(xb + c);
    float4 x1 = *(const float4*)(xb + C_ + c);
    float4 x2 = *(const float4*)(xb + 24 * C_ + c);
    float4 x3 = *(const float4*)(xb + 25 * C_ + c);

    float s0 = rv.x * x0.x + rv.y * x0.y + rv.z * x0.z + rv.w * x0.w;
    float s1 = rv.x * x1.x + rv.y * x1.y + rv.z * x1.z + rv.w * x1.w;
    float s2 = rv.x * x2.x + rv.y * x2.y + rv.z * x2.z + rv.w * x2.w;
    float s3 = rv.x * x3.x + rv.y * x3.y + rv.z * x3.z + rv.w * x3.w;
    float qb = g_q[(size_t)row * MID_ + tid] * bk[tid];

#pragma unroll
    for (int off = 16; off > 0; off >>= 1) {
        s0 += __shfl_down_sync(0xffffffff, s0, off);
        s1 += __shfl_down_sync(0xffffffff, s1, off);
        s2 += __shfl_down_sync(0xffffffff, s2, off);
        s3 += __shfl_down_sync(0xffffffff, s3, off);
        qb += __shfl_down_sync(0xffffffff, qb, off);
    }

    __shared__ float red[8][5];
    __shared__ float coef[4];
    int lane = tid & 31, warp = tid >> 5;
    if (lane == 0) {
        red[warp][0] = s0; red[warp][1] = s1; red[warp][2] = s2;
        red[warp][3] = s3; red[warp][4] = qb;
    }
    __syncthreads();
    if (tid == 0) {
        float S[5] = {0.f, 0.f, 0.f, 0.f, 0.f};
#pragma unroll
        for (int w = 0; w < 8; w++)
#pragma unroll
            for (int k = 0; k < 5; k++) S[k] += red[w][k];
        const float scale = 0.0625f;  // 1/sqrt(256)
        float l0 = (S[0] + S[4]) * scale;
        float l1 = (S[1] + S[4]) * scale;
        float l2 = (S[2] + S[4]) * scale;
        float l3 = (S[3] + S[4]) * scale;
        float m = fmaxf(fmaxf(l0, l1), fmaxf(l2, l3));
        float e0 = expf(l0 - m), e1 = expf(l1 - m);
        float e2 = expf(l2 - m), e3 = expf(l3 - m);
        float inv = 1.0f / (e0 + e1 + e2 + e3);
        coef[0] = 0.25f + e0 * inv;
        coef[1] = 0.25f + e1 * inv;
        coef[2] = 0.25f + e2 * inv;
        coef[3] = 0.25f + e3 * inv;
    }
    __syncthreads();
    float c0 = coef[0], c1 = coef[1], c2 = coef[2], c3 = coef[3];
    float4 o;
    o.x = c0 * x0.x + c1 * x1.x + c2 * x2.x + c3 * x3.x;
    o.y = c0 * x0.y + c1 * x1.y + c2 * x2.y + c3 * x3.y;
    o.z = c0 * x0.z + c1 * x1.z + c2 * x2.z + c3 * x3.z;
    o.w = c0 * x0.w + c1 * x1.w + c2 * x2.w + c3 * x3.w;
    *(float4*)(out + (size_t)row * C_ + c) = o;
}

// ---------------- launch ----------------
extern "C" void kernel_launch(void* const* d_in, const int* in_sizes, int n_in,
                              void* d_out, int out_size) {
    const float* x  = (const float*)d_in[0];  // [64, 576, 1024]
    const float* Wq = (const float*)d_in[1];  // [1024, 256]
    const float* bq = (const float*)d_in[2];  // [256]
    const float* Wk = (const float*)d_in[3];  // [1024, 256]
    const float* bk = (const float*)d_in[4];  // [256]
    float* out = (float*)d_out;               // [64, 144, 1024]

    float* pooled; cudaGetSymbolAddress((void**)&pooled, g_pooled);
    float* q;      cudaGetSymbolAddress((void**)&q, g_q);
    float* r;      cudaGetSymbolAddress((void**)&r, g_r);
    float* wt;     cudaGetSymbolAddress((void**)&wt, g_WT);
    float* wkr;    cudaGetSymbolAddress((void**)&wkr, g_WkR);

    pool_kernel<<<ROWS, 256>>>(x);
    transpose_w<<<dim3(32, 8), dim3(32, 8)>>>(Wq);
    round_wk<<<256, 256>>>(Wk);
    // q[9216,256] = pooled @ Wq + bq  (B = Wq^T rows K-major; q tf32-rounded out)
    gemm_cp<true, true><<<dim3(MID_ / 64, ROWS / 128), 128>>>(pooled, wt, bq, q, MID_, C_);
    // r[9216,1024] = q @ Wk^T          (B = rounded Wk, K-major rows)
    gemm_cp<false, false><<<dim3(C_ / 64, ROWS / 128), 128>>>(q, wkr, nullptr, r, C_, MID_);
    attn_kernel<<<ROWS, 256>>>(x, bk, out);
}